// round 12
// baseline (speedup 1.0000x reference)
#include <cuda_runtime.h>
#include <cuda_fp16.h>
#include <cstdint>

#define BATCH  256
#define PART   128
#define ONODES 64
#define INODES 64
#define BT     32
#define NT     128

__device__ __forceinline__ uint32_t smem_u32(const void* p) {
    uint32_t a;
    asm("{ .reg .u64 t; cvta.to.shared.u64 t, %1; cvt.u32.u64 %0, t; }"
        : "=r"(a) : "l"(p));
    return a;
}
__device__ __forceinline__ void ldsm_x4(uint32_t& r0, uint32_t& r1,
                                        uint32_t& r2, uint32_t& r3,
                                        uint32_t addr) {
    asm volatile("ldmatrix.sync.aligned.m8n8.x4.shared.b16 {%0,%1,%2,%3}, [%4];"
                 : "=r"(r0), "=r"(r1), "=r"(r2), "=r"(r3) : "r"(addr));
}
__device__ __forceinline__ void mma16816(float* d, uint32_t a0, uint32_t a1,
                                         uint32_t a2, uint32_t a3,
                                         uint32_t b0, uint32_t b1) {
    asm volatile(
        "mma.sync.aligned.m16n8k16.row.col.f32.f16.f16.f32 "
        "{%0,%1,%2,%3}, {%4,%5,%6,%7}, {%8,%9}, {%0,%1,%2,%3};"
        : "+f"(d[0]), "+f"(d[1]), "+f"(d[2]), "+f"(d[3])
        : "r"(a0), "r"(a1), "r"(a2), "r"(a3), "r"(b0), "r"(b1));
}
__device__ __forceinline__ uint32_t h2bits(float a, float b) {
    __half2 h = __floats2half2_rn(a, b);
    return *reinterpret_cast<uint32_t*>(&h);
}
__device__ __forceinline__ void split4(float e0, float e1, float e2, float e3,
                                       uint32_t& h01, uint32_t& h23,
                                       uint32_t& r01, uint32_t& r23) {
    __half2 H01 = __floats2half2_rn(e0, e1);
    __half2 H23 = __floats2half2_rn(e2, e3);
    float2 f01 = __half22float2(H01);
    float2 f23 = __half22float2(H23);
    h01 = *reinterpret_cast<uint32_t*>(&H01);
    h23 = *reinterpret_cast<uint32_t*>(&H23);
    r01 = h2bits(e0 - f01.x, e1 - f01.y);
    r23 = h2bits(e2 - f23.x, e3 - f23.y);
}

// SW128 swizzle relative to a 128B-aligned tile with 128B rows:
// swz(row*128 + c) = row*128 + (c ^ ((row&7)<<4))

// out[b,p,o] = log( sum_i exp(x[b,p,i]) * softmax_i(weight[p,o,:]) )
// GEMM on HMMA (mma.sync m16n8k16), fp16 hi+residual split:
//   D = Ah*Bh + Ar*Bh + Ah*Br  (fp32 accum)
__global__ __launch_bounds__(NT)
void sumlayer_kernel(const float* __restrict__ x,
                     const float* __restrict__ weight,
                     float* __restrict__ out) {
    __shared__ __align__(1024) __half sAh[BT * 64];      // [r][i] 4KB
    __shared__ __align__(1024) __half sAr[BT * 64];      // 4KB
    __shared__ __align__(1024) __half sBh[ONODES * 64];  // [o][i] 8KB
    __shared__ __align__(1024) __half sBr[ONODES * 64];  // 8KB

    const int p   = blockIdx.y;
    const int b0  = blockIdx.x * BT;
    const int tid = threadIdx.x;

    // -- prefetch (12 independent LDG.128) ----------------------------------
    const int o  = tid >> 1;             // 0..63 (W row)
    const int jw = tid & 1;              // 32-i half
    const int r  = tid >> 2;             // 0..31 (X row)
    const int jx = tid & 3;              // 16-i quarter
    const float4* wrow = reinterpret_cast<const float4*>(
        weight + ((size_t)p * ONODES + o) * INODES + jw * 32);
    const float4* xrow = reinterpret_cast<const float4*>(
        x + ((size_t)(b0 + r) * PART + p) * INODES + jx * 16);
    float4 w4[8], x4[4];
    #pragma unroll
    for (int q = 0; q < 8; q++) w4[q] = wrow[q];
    #pragma unroll
    for (int q = 0; q < 4; q++) x4[q] = xrow[q];

    // -- phase W: softmax (no max shift: |w| <= ~0.6) -> Bh/Br [o][i] -------
    {
        float v[32];
        #pragma unroll
        for (int q = 0; q < 8; q++) {
            v[4*q+0] = w4[q].x; v[4*q+1] = w4[q].y;
            v[4*q+2] = w4[q].z; v[4*q+3] = w4[q].w;
        }
        float s = 0.0f;
        #pragma unroll
        for (int q = 0; q < 32; q++) { v[q] = __expf(v[q]); s += v[q]; }
        s += __shfl_xor_sync(0xffffffffu, s, 1);
        float inv = __fdividef(1.0f, s);
        #pragma unroll
        for (int q = 0; q < 32; q++) v[q] *= inv;

        uint32_t hh[16], rr[16];
        #pragma unroll
        for (int q = 0; q < 8; q++)
            split4(v[4*q], v[4*q+1], v[4*q+2], v[4*q+3],
                   hh[2*q], hh[2*q+1], rr[2*q], rr[2*q+1]);

        const uint32_t xorc = (uint32_t)((o & 7) << 4);
        const uint32_t base = (uint32_t)(o * 128 + jw * 64);
        char* bh = reinterpret_cast<char*>(sBh);
        char* br = reinterpret_cast<char*>(sBr);
        #pragma unroll
        for (int q = 0; q < 4; q++) {
            *reinterpret_cast<uint4*>(bh + ((base + q * 16) ^ xorc)) =
                make_uint4(hh[4*q], hh[4*q+1], hh[4*q+2], hh[4*q+3]);
            *reinterpret_cast<uint4*>(br + ((base + q * 16) ^ xorc)) =
                make_uint4(rr[4*q], rr[4*q+1], rr[4*q+2], rr[4*q+3]);
        }
    }

    // -- phase X: exp(x) -> Ah/Ar [r][i] fp16 -------------------------------
    {
        uint32_t hh[8], rr[8];
        #pragma unroll
        for (int q = 0; q < 4; q++) {
            split4(__expf(x4[q].x), __expf(x4[q].y),
                   __expf(x4[q].z), __expf(x4[q].w),
                   hh[2*q], hh[2*q+1], rr[2*q], rr[2*q+1]);
        }
        const uint32_t xorc = (uint32_t)((r & 7) << 4);
        const uint32_t base = (uint32_t)(r * 128 + jx * 32);
        char* ah = reinterpret_cast<char*>(sAh);
        char* ar = reinterpret_cast<char*>(sAr);
        *reinterpret_cast<uint4*>(ah + (base ^ xorc))        = make_uint4(hh[0], hh[1], hh[2], hh[3]);
        *reinterpret_cast<uint4*>(ah + ((base + 16) ^ xorc)) = make_uint4(hh[4], hh[5], hh[6], hh[7]);
        *reinterpret_cast<uint4*>(ar + (base ^ xorc))        = make_uint4(rr[0], rr[1], rr[2], rr[3]);
        *reinterpret_cast<uint4*>(ar + ((base + 16) ^ xorc)) = make_uint4(rr[4], rr[5], rr[6], rr[7]);
    }
    __syncthreads();

    // -- GEMM via mma.sync: 4 warps, warp = m16 x n32 -----------------------
    const int wid = tid >> 5;
    const int lid = tid & 31;
    const int wm  = (wid & 1) * 16;      // m strip (M=32)
    const int wn  = (wid >> 1) * 32;     // n strip (N=64)

    const int lrow = lid & 15;
    const uint32_t lkh  = (uint32_t)((lid >> 4) * 16);
    const uint32_t lxor = (uint32_t)((lrow & 7) << 4);

    const uint32_t aRow  = (uint32_t)((wm + lrow) * 128);
    const uint32_t bRow0 = (uint32_t)((wn + lrow) * 128);
    const uint32_t bRow1 = (uint32_t)((wn + 16 + lrow) * 128);

    const uint32_t sAh0 = smem_u32(sAh), sAr0 = smem_u32(sAr);
    const uint32_t sBh0 = smem_u32(sBh), sBr0 = smem_u32(sBr);

    float acc[4][4] = {};

    #pragma unroll
    for (int k = 0; k < 4; k++) {
        const uint32_t kc = ((uint32_t)(k * 32) + lkh) ^ lxor;

        uint32_t ah0, ah1, ah2, ah3, ar0, ar1, ar2, ar3;
        ldsm_x4(ah0, ah1, ah2, ah3, sAh0 + aRow + kc);
        ldsm_x4(ar0, ar1, ar2, ar3, sAr0 + aRow + kc);

        uint32_t p0, p1, p2, p3, q0, q1, q2, q3;
        ldsm_x4(p0, p1, p2, p3, sBh0 + bRow0 + kc);
        ldsm_x4(q0, q1, q2, q3, sBh0 + bRow1 + kc);

        mma16816(acc[0], ah0, ah1, ah2, ah3, p0, p2);
        mma16816(acc[1], ah0, ah1, ah2, ah3, p1, p3);
        mma16816(acc[2], ah0, ah1, ah2, ah3, q0, q2);
        mma16816(acc[3], ah0, ah1, ah2, ah3, q1, q3);
        mma16816(acc[0], ar0, ar1, ar2, ar3, p0, p2);
        mma16816(acc[1], ar0, ar1, ar2, ar3, p1, p3);
        mma16816(acc[2], ar0, ar1, ar2, ar3, q0, q2);
        mma16816(acc[3], ar0, ar1, ar2, ar3, q1, q3);

        ldsm_x4(p0, p1, p2, p3, sBr0 + bRow0 + kc);
        ldsm_x4(q0, q1, q2, q3, sBr0 + bRow1 + kc);
        mma16816(acc[0], ah0, ah1, ah2, ah3, p0, p2);
        mma16816(acc[1], ah0, ah1, ah2, ah3, p1, p3);
        mma16816(acc[2], ah0, ah1, ah2, ah3, q0, q2);
        mma16816(acc[3], ah0, ah1, ah2, ah3, q1, q3);
    }

    // -- epilogue: out = log(acc) ------------------------------------------
    const int rA = wm + (lid >> 2);
    const int cP = (lid & 3) * 2;
    #pragma unroll
    for (int t = 0; t < 4; t++) {
        const int col = wn + t * 8 + cP;
        float2 lo, hi;
        lo.x = __logf(acc[t][0]); lo.y = __logf(acc[t][1]);
        hi.x = __logf(acc[t][2]); hi.y = __logf(acc[t][3]);
        *reinterpret_cast<float2*>(
            &out[((size_t)(b0 + rA) * PART + p) * ONODES + col]) = lo;
        *reinterpret_cast<float2*>(
            &out[((size_t)(b0 + rA + 8) * PART + p) * ONODES + col]) = hi;
    }
}

extern "C" void kernel_launch(void* const* d_in, const int* in_sizes, int n_in,
                              void* d_out, int out_size) {
    const float* x      = (const float*)d_in[0];   // [256,128,64]
    const float* weight = (const float*)d_in[1];   // [128,64,64]
    float* out          = (float*)d_out;           // [256,128,64]

    sumlayer_kernel<<<dim3(BATCH / BT, PART), NT>>>(x, weight, out);
}

// round 13
// speedup vs baseline: 1.4018x; 1.4018x over previous
#include <cuda_runtime.h>
#include <cuda_fp16.h>
#include <cstdint>

#define BATCH  256
#define PART   128
#define ONODES 64
#define INODES 64
#define BT     64
#define NT     256

__device__ __forceinline__ uint32_t smem_u32(const void* p) {
    uint32_t a;
    asm("{ .reg .u64 t; cvta.to.shared.u64 t, %1; cvt.u32.u64 %0, t; }"
        : "=r"(a) : "l"(p));
    return a;
}
__device__ __forceinline__ void ldsm_x4(uint32_t& r0, uint32_t& r1,
                                        uint32_t& r2, uint32_t& r3,
                                        uint32_t addr) {
    asm volatile("ldmatrix.sync.aligned.m8n8.x4.shared.b16 {%0,%1,%2,%3}, [%4];"
                 : "=r"(r0), "=r"(r1), "=r"(r2), "=r"(r3) : "r"(addr));
}
__device__ __forceinline__ void mma16816(float* d, uint32_t a0, uint32_t a1,
                                         uint32_t a2, uint32_t a3,
                                         uint32_t b0, uint32_t b1) {
    asm volatile(
        "mma.sync.aligned.m16n8k16.row.col.f32.f16.f16.f32 "
        "{%0,%1,%2,%3}, {%4,%5,%6,%7}, {%8,%9}, {%0,%1,%2,%3};"
        : "+f"(d[0]), "+f"(d[1]), "+f"(d[2]), "+f"(d[3])
        : "r"(a0), "r"(a1), "r"(a2), "r"(a3), "r"(b0), "r"(b1));
}
__device__ __forceinline__ uint32_t h2bits(float a, float b) {
    __half2 h = __floats2half2_rn(a, b);
    return *reinterpret_cast<uint32_t*>(&h);
}
// pack 4 floats -> hi halves and residual halves (A operand only)
__device__ __forceinline__ void split4(float e0, float e1, float e2, float e3,
                                       uint32_t& h01, uint32_t& h23,
                                       uint32_t& r01, uint32_t& r23) {
    __half2 H01 = __floats2half2_rn(e0, e1);
    __half2 H23 = __floats2half2_rn(e2, e3);
    float2 f01 = __half22float2(H01);
    float2 f23 = __half22float2(H23);
    h01 = *reinterpret_cast<uint32_t*>(&H01);
    h23 = *reinterpret_cast<uint32_t*>(&H23);
    r01 = h2bits(e0 - f01.x, e1 - f01.y);
    r23 = h2bits(e2 - f23.x, e3 - f23.y);
}

// SW128 swizzle relative to a 128B-aligned tile with 128B rows:
// swz(row*128 + c) = row*128 + (c ^ ((row&7)<<4))

// out[b,p,o] = log( sum_i exp(x[b,p,i]) * softmax_i(weight[p,o,:]) )
// GEMM on HMMA (mma.sync m16n8k16), A split hi+residual, B fp16:
//   D = Ah*Bh + Ar*Bh      (fp32 accum; error <= max|Br/B| ~ 2^-11 < 1e-3)
__global__ __launch_bounds__(NT)
void sumlayer_kernel(const float* __restrict__ x,
                     const float* __restrict__ weight,
                     float* __restrict__ out) {
    __shared__ __align__(1024) __half sAh[BT * 64];      // [r][i] 8KB
    __shared__ __align__(1024) __half sAr[BT * 64];      // 8KB
    __shared__ __align__(1024) __half sBh[ONODES * 64];  // [o][i] 8KB

    const int p   = blockIdx.y;
    const int b0  = blockIdx.x * BT;
    const int tid = threadIdx.x;

    // -- prefetch: 8 independent LDG.128 ------------------------------------
    const int o = tid >> 2;              // 0..63 (also batch row r)
    const int j = tid & 3;               // 16-i quarter
    const float4* wrow = reinterpret_cast<const float4*>(
        weight + ((size_t)p * ONODES + o) * INODES + j * 16);
    const float4* xrow = reinterpret_cast<const float4*>(
        x + ((size_t)(b0 + o) * PART + p) * INODES + j * 16);
    float4 w4[4], x4[4];
    #pragma unroll
    for (int q = 0; q < 4; q++) w4[q] = wrow[q];
    #pragma unroll
    for (int q = 0; q < 4; q++) x4[q] = xrow[q];

    // -- phase W: softmax (no max shift: |w| <= ~0.6) -> Bh [o][i] ----------
    {
        float v[16];
        #pragma unroll
        for (int q = 0; q < 4; q++) {
            v[4*q+0] = w4[q].x; v[4*q+1] = w4[q].y;
            v[4*q+2] = w4[q].z; v[4*q+3] = w4[q].w;
        }
        float s = 0.0f;
        #pragma unroll
        for (int q = 0; q < 16; q++) { v[q] = __expf(v[q]); s += v[q]; }
        s += __shfl_xor_sync(0xffffffffu, s, 1);
        s += __shfl_xor_sync(0xffffffffu, s, 2);
        float inv = __fdividef(1.0f, s);

        uint32_t hh[8];
        #pragma unroll
        for (int q = 0; q < 4; q++) {
            hh[2*q]   = h2bits(v[4*q]   * inv, v[4*q+1] * inv);
            hh[2*q+1] = h2bits(v[4*q+2] * inv, v[4*q+3] * inv);
        }

        const uint32_t xorc = (uint32_t)((o & 7) << 4);
        const uint32_t base = (uint32_t)(o * 128 + j * 32);
        char* bh = reinterpret_cast<char*>(sBh);
        *reinterpret_cast<uint4*>(bh + (base ^ xorc))        = make_uint4(hh[0], hh[1], hh[2], hh[3]);
        *reinterpret_cast<uint4*>(bh + ((base + 16) ^ xorc)) = make_uint4(hh[4], hh[5], hh[6], hh[7]);
    }

    // -- phase X: exp(x) -> Ah/Ar [r][i] fp16 -------------------------------
    {
        uint32_t hh[8], rr[8];
        #pragma unroll
        for (int q = 0; q < 4; q++) {
            split4(__expf(x4[q].x), __expf(x4[q].y),
                   __expf(x4[q].z), __expf(x4[q].w),
                   hh[2*q], hh[2*q+1], rr[2*q], rr[2*q+1]);
        }
        const uint32_t xorc = (uint32_t)((o & 7) << 4);
        const uint32_t base = (uint32_t)(o * 128 + j * 32);
        char* ah = reinterpret_cast<char*>(sAh);
        char* ar = reinterpret_cast<char*>(sAr);
        *reinterpret_cast<uint4*>(ah + (base ^ xorc))        = make_uint4(hh[0], hh[1], hh[2], hh[3]);
        *reinterpret_cast<uint4*>(ah + ((base + 16) ^ xorc)) = make_uint4(hh[4], hh[5], hh[6], hh[7]);
        *reinterpret_cast<uint4*>(ar + (base ^ xorc))        = make_uint4(rr[0], rr[1], rr[2], rr[3]);
        *reinterpret_cast<uint4*>(ar + ((base + 16) ^ xorc)) = make_uint4(rr[4], rr[5], rr[6], rr[7]);
    }
    __syncthreads();

    // -- GEMM via mma.sync: warp (wm 16 rows) x (wn 32 cols) ----------------
    const int wid = tid >> 5;
    const int lid = tid & 31;
    const int wm  = (wid & 3) * 16;      // m strip
    const int wn  = (wid >> 2) * 32;     // n strip

    const int lrow = lid & 15;
    const uint32_t lkh  = (uint32_t)((lid >> 4) * 16);   // k-half 16B
    const uint32_t lxor = (uint32_t)((lrow & 7) << 4);

    const uint32_t aRow  = (uint32_t)((wm + lrow) * 128);
    const uint32_t bRow0 = (uint32_t)((wn + lrow) * 128);        // n 0-15
    const uint32_t bRow1 = (uint32_t)((wn + 16 + lrow) * 128);   // n 16-31

    const uint32_t sAh0 = smem_u32(sAh), sAr0 = smem_u32(sAr);
    const uint32_t sBh0 = smem_u32(sBh);

    float acc[4][4] = {};                // 4 n8-tiles x 4 regs

    #pragma unroll
    for (int k = 0; k < 4; k++) {
        const uint32_t kc = ((uint32_t)(k * 32) + lkh) ^ lxor;

        uint32_t ah0, ah1, ah2, ah3, ar0, ar1, ar2, ar3;
        ldsm_x4(ah0, ah1, ah2, ah3, sAh0 + aRow + kc);
        ldsm_x4(ar0, ar1, ar2, ar3, sAr0 + aRow + kc);

        // B: [n][k] row-major + non-trans ldmatrix = exact b-frag mapping
        uint32_t p0, p1, p2, p3, q0, q1, q2, q3;
        ldsm_x4(p0, p1, p2, p3, sBh0 + bRow0 + kc);   // n tiles 0,1
        ldsm_x4(q0, q1, q2, q3, sBh0 + bRow1 + kc);   // n tiles 2,3

        mma16816(acc[0], ah0, ah1, ah2, ah3, p0, p2);
        mma16816(acc[1], ah0, ah1, ah2, ah3, p1, p3);
        mma16816(acc[2], ah0, ah1, ah2, ah3, q0, q2);
        mma16816(acc[3], ah0, ah1, ah2, ah3, q1, q3);
        mma16816(acc[0], ar0, ar1, ar2, ar3, p0, p2);
        mma16816(acc[1], ar0, ar1, ar2, ar3, p1, p3);
        mma16816(acc[2], ar0, ar1, ar2, ar3, q0, q2);
        mma16816(acc[3], ar0, ar1, ar2, ar3, q1, q3);
    }

    // -- epilogue: out = log(acc) ------------------------------------------
    // d-frag: lane -> rows (lid>>2), (lid>>2)+8; cols (lid&3)*2, +1
    const int rA = wm + (lid >> 2);
    const int cP = (lid & 3) * 2;
    #pragma unroll
    for (int t = 0; t < 4; t++) {
        const int col = wn + t * 8 + cP;
        float2 lo, hi;
        lo.x = __logf(acc[t][0]); lo.y = __logf(acc[t][1]);
        hi.x = __logf(acc[t][2]); hi.y = __logf(acc[t][3]);
        *reinterpret_cast<float2*>(
            &out[((size_t)(b0 + rA) * PART + p) * ONODES + col]) = lo;
        *reinterpret_cast<float2*>(
            &out[((size_t)(b0 + rA + 8) * PART + p) * ONODES + col]) = hi;
    }
}

extern "C" void kernel_launch(void* const* d_in, const int* in_sizes, int n_in,
                              void* d_out, int out_size) {
    const float* x      = (const float*)d_in[0];   // [256,128,64]
    const float* weight = (const float*)d_in[1];   // [128,64,64]
    float* out          = (float*)d_out;           // [256,128,64]

    sumlayer_kernel<<<dim3(BATCH / BT, PART), NT>>>(x, weight, out);
}